// round 7
// baseline (speedup 1.0000x reference)
#include <cuda_runtime.h>
#include <math_constants.h>

#define NN 100000
#define FI 256
#define FH 128
#define FO 40
#define EMAX 1700000

typedef unsigned long long u64;

// ---------------- scratch (static device globals; zero-init at load) --------
__device__ int   g_cnt[NN];        // degree counts (restored to 0 each call)
__device__ int   g_rowp[NN];       // CSR row start
__device__ int   g_cur[NN];        // fill cursor; after fill == row end
__device__ int   g_nbr[EMAX];      // CSR neighbor (src) ids
__device__ int   g_alloc;          // row allocation cursor
__device__ __align__(256) float g_dinv[NN];
__device__ __align__(256) float g_h1[NN * FH];
__device__ __align__(256) float g_agg1[NN * FH];
__device__ __align__(256) float g_h2[NN * FO];
__device__ __align__(256) float g_agg2[NN * FO];

// ---------------- packed fp32x2 helpers -------------------------------------
__device__ __forceinline__ u64 pack2(float lo, float hi) {
    u64 r; asm("mov.b64 %0, {%1, %2};" : "=l"(r) : "f"(lo), "f"(hi)); return r;
}
__device__ __forceinline__ float2 unpack2(u64 v) {
    float2 f; asm("mov.b64 {%0, %1}, %2;" : "=f"(f.x), "=f"(f.y) : "l"(v)); return f;
}
__device__ __forceinline__ u64 ffma2(u64 a, u64 b, u64 c) {
    u64 d; asm("fma.rn.f32x2 %0, %1, %2, %3;" : "=l"(d) : "l"(a), "l"(b), "l"(c)); return d;
}
// dtype probe: int32 data viewed as int64 has random hi-words -> out of range.
__device__ __forceinline__ int probe64(const void* ei) {
    const long long* p = (const long long*)ei;
    int ok = 1;
    #pragma unroll
    for (int j = 0; j < 8; j++) {
        long long v = p[j];
        if (v < 0 || v >= NN) ok = 0;
    }
    return ok;
}
__device__ __forceinline__ int eidx(const void* p, long long i, int is64) {
    if (is64) return (int)((const long long*)p)[i];
    return ((const int*)p)[i];
}

// ---------------- CSR build --------------------------------------------------
__global__ void k_deg(const void* ei, int E) {
    int i = blockIdx.x * blockDim.x + threadIdx.x;
    if (i == 0) g_alloc = 0;                     // reset allocator (pre-rowp)
    int is64 = probe64(ei);
    if (i < E) {
        int d = eidx(ei, (long long)E + i, is64);
        atomicAdd(&g_cnt[d], 1);
    }
}

__global__ void k_rowp() {
    int i = blockIdx.x * blockDim.x + threadIdx.x;
    if (i < NN) {
        int c = g_cnt[i];
        int start = atomicAdd(&g_alloc, c);      // order-free row allocation
        g_rowp[i] = start;
        g_cur[i]  = start;
        g_dinv[i] = rsqrtf((float)c + 1.0f);     // +1 self loop
        g_cnt[i]  = 0;                           // restore for next call
    }
}

__global__ void k_fill(const void* ei, int E) {
    int i = blockIdx.x * blockDim.x + threadIdx.x;
    int is64 = probe64(ei);
    if (i < E) {
        int s = eidx(ei, i, is64);
        int d = eidx(ei, (long long)E + i, is64);
        int p = atomicAdd(&g_cur[d], 1);
        g_nbr[p] = s;
    }
}

// ---------------- GEMM1: h1 = x @ W1  (100000x256 @ 256x128) ----------------
// 128 thr = 4 warps; warp tg rows tg*16..+15 (64 rows/blk); lane tx colpairs
// {tx, tx+32}. Ws2[k][cp] conflict-free LDS.64; Xs2[r][k] dup-pack broadcast.
// Small CTA + reg cap => 5 CTAs/SM (20 warps) to hide LDS latency.
__global__ void __launch_bounds__(128, 5) k_gemm1(const float* __restrict__ x,
                                                  const float* __restrict__ W1) {
    __shared__ u64 Ws2[32 * 64];   // 16 KB
    __shared__ u64 Xs2[64 * 32];   // 16 KB
    int t = threadIdx.x;
    int tx = t & 31, tg = t >> 5;
    int row0 = blockIdx.x * 64;

    u64 acc[2][16];
    #pragma unroll
    for (int c = 0; c < 2; c++)
        #pragma unroll
        for (int r = 0; r < 16; r++) acc[c][r] = 0ULL;

    for (int kt = 0; kt < 8; kt++) {
        const float2* Wg = (const float2*)(W1 + (size_t)(kt * 32) * 128);
        #pragma unroll
        for (int i = t; i < 2048; i += 128) {
            float2 w = Wg[i];               // i = k*64 + cp
            Ws2[i] = pack2(w.x, w.y);
        }
        #pragma unroll
        for (int i = t; i < 2048; i += 128) {
            int r = i >> 5, k = i & 31;
            int row = row0 + r; if (row >= NN) row = NN - 1;
            float v = x[(size_t)row * FI + kt * 32 + k];
            Xs2[i] = pack2(v, v);
        }
        __syncthreads();

        #pragma unroll
        for (int k = 0; k < 32; k += 2) {
            u64 w00 = Ws2[k * 64 + tx];
            u64 w01 = Ws2[k * 64 + tx + 32];
            u64 w10 = Ws2[(k + 1) * 64 + tx];
            u64 w11 = Ws2[(k + 1) * 64 + tx + 32];
            #pragma unroll
            for (int r = 0; r < 16; r++) {
                ulonglong2 xv = *(const ulonglong2*)&Xs2[(tg * 16 + r) * 32 + k];
                acc[0][r] = ffma2(xv.x, w00, acc[0][r]);
                acc[1][r] = ffma2(xv.x, w01, acc[1][r]);
                acc[0][r] = ffma2(xv.y, w10, acc[0][r]);
                acc[1][r] = ffma2(xv.y, w11, acc[1][r]);
            }
        }
        __syncthreads();
    }

    #pragma unroll
    for (int r = 0; r < 16; r++) {
        int row = row0 + tg * 16 + r;
        if (row < NN) {
            #pragma unroll
            for (int c = 0; c < 2; c++) {
                ((float2*)g_h1)[(size_t)row * 64 + tx + c * 32] = unpack2(acc[c][r]);
            }
        }
    }
}

// ---------------- layer-1 aggregate: warp-per-dst CSR gather -----------------
// agg1[d] = b1 + dinv[d]^2 * h1[d] + sum_{s in N(d)} dinv[d]*dinv[s]*h1[s]
__global__ void __launch_bounds__(256) k_agg1(const float* __restrict__ b1) {
    int w = (blockIdx.x * 256 + threadIdx.x) >> 5;
    int lane = threadIdx.x & 31;
    if (w >= NN) return;
    int e = g_rowp[w], end = g_cur[w];
    float did = g_dinv[w];
    const float4* H = (const float4*)g_h1;

    float4 acc = ((const float4*)b1)[lane];
    float4 self = H[(size_t)w * 32 + lane];
    float d2 = did * did;
    acc.x = fmaf(self.x, d2, acc.x);
    acc.y = fmaf(self.y, d2, acc.y);
    acc.z = fmaf(self.z, d2, acc.z);
    acc.w = fmaf(self.w, d2, acc.w);

    int s = (e < end) ? g_nbr[e] : 0;
    while (e < end) {
        int sn = (e + 1 < end) ? g_nbr[e + 1] : 0;
        float nm = did * g_dinv[s];
        float4 v = H[(size_t)s * 32 + lane];
        acc.x = fmaf(v.x, nm, acc.x);
        acc.y = fmaf(v.y, nm, acc.y);
        acc.z = fmaf(v.z, nm, acc.z);
        acc.w = fmaf(v.w, nm, acc.w);
        s = sn;
        e++;
    }
    ((float4*)g_agg1)[(size_t)w * 32 + lane] = acc;
}

// ---------------- GEMM2: h2 = relu(agg1) @ W2  (100000x128 @ 128x40) --------
__global__ void __launch_bounds__(160, 4) k_gemm2(const float* __restrict__ W2) {
    __shared__ u64 Ws2[64 * 20];   // 10 KB
    __shared__ u64 Xs2[64 * 64];   // 32 KB
    int t = threadIdx.x;
    int tx = t % 20, tg = t / 20;
    int row0 = blockIdx.x * 64;

    u64 acc[8];
    #pragma unroll
    for (int r = 0; r < 8; r++) acc[r] = 0ULL;

    for (int kt = 0; kt < 2; kt++) {
        const float2* Wg = (const float2*)(W2 + (size_t)(kt * 64) * 40);
        for (int i = t; i < 1280; i += 160) {
            float2 w = Wg[i];               // i = k*20 + cp
            Ws2[i] = pack2(w.x, w.y);
        }
        for (int i = t; i < 4096; i += 160) {
            int r = i >> 6, k = i & 63;
            int row = row0 + r; if (row >= NN) row = NN - 1;
            float v = fmaxf(g_agg1[(size_t)row * FH + kt * 64 + k], 0.f);
            Xs2[i] = pack2(v, v);
        }
        __syncthreads();

        #pragma unroll
        for (int k = 0; k < 64; k += 2) {
            u64 w0 = Ws2[k * 20 + tx];
            u64 w1 = Ws2[(k + 1) * 20 + tx];
            #pragma unroll
            for (int r = 0; r < 8; r++) {
                ulonglong2 xv = *(const ulonglong2*)&Xs2[(tg * 8 + r) * 64 + k];
                acc[r] = ffma2(xv.x, w0, acc[r]);
                acc[r] = ffma2(xv.y, w1, acc[r]);
            }
        }
        __syncthreads();
    }

    #pragma unroll
    for (int r = 0; r < 8; r++) {
        int row = row0 + tg * 8 + r;
        if (row < NN)
            ((float2*)g_h2)[(size_t)row * 20 + tx] = unpack2(acc[r]);
    }
}

// ---------------- layer-2 aggregate: 10-threads-per-dst CSR gather -----------
__global__ void __launch_bounds__(320) k_agg2(const float* __restrict__ b2) {
    int idx = blockIdx.x * 320 + threadIdx.x;
    int w = idx / 10, c = idx % 10;
    if (w >= NN) return;
    int e = g_rowp[w], end = g_cur[w];
    float did = g_dinv[w];
    const float4* H = (const float4*)g_h2;

    float4 acc = ((const float4*)b2)[c];
    float4 self = H[(size_t)w * 10 + c];
    float d2 = did * did;
    acc.x = fmaf(self.x, d2, acc.x);
    acc.y = fmaf(self.y, d2, acc.y);
    acc.z = fmaf(self.z, d2, acc.z);
    acc.w = fmaf(self.w, d2, acc.w);

    int s = (e < end) ? g_nbr[e] : 0;
    while (e < end) {
        int sn = (e + 1 < end) ? g_nbr[e + 1] : 0;
        float nm = did * g_dinv[s];
        float4 v = H[(size_t)s * 10 + c];
        acc.x = fmaf(v.x, nm, acc.x);
        acc.y = fmaf(v.y, nm, acc.y);
        acc.z = fmaf(v.z, nm, acc.z);
        acc.w = fmaf(v.w, nm, acc.w);
        s = sn;
        e++;
    }
    ((float4*)g_agg2)[(size_t)w * 10 + c] = acc;
}

// ---------------- log_softmax, warp per row ----------------------------------
__global__ void k_lsm(float* __restrict__ out) {
    int row = (blockIdx.x * blockDim.x + threadIdx.x) >> 5;
    int lane = threadIdx.x & 31;
    if (row < NN) {
        const float* in = g_agg2 + (size_t)row * FO;
        float v0 = in[lane];
        float v1 = (lane < 8) ? in[32 + lane] : -CUDART_INF_F;
        float m = fmaxf(v0, v1);
        #pragma unroll
        for (int o = 16; o; o >>= 1) m = fmaxf(m, __shfl_xor_sync(0xffffffffu, m, o));
        float s = expf(v0 - m) + ((lane < 8) ? expf(v1 - m) : 0.f);
        #pragma unroll
        for (int o = 16; o; o >>= 1) s += __shfl_xor_sync(0xffffffffu, s, o);
        float ls = m + logf(s);
        out[(size_t)row * FO + lane] = v0 - ls;
        if (lane < 8) out[(size_t)row * FO + 32 + lane] = v1 - ls;
    }
}

// ---------------- launch ------------------------------------------------------
extern "C" void kernel_launch(void* const* d_in, const int* in_sizes, int n_in,
                              void* d_out, int out_size) {
    const float* x  = (const float*)d_in[0];
    const void*  ei = d_in[1];
    const float* W1 = (const float*)d_in[2];
    const float* b1 = (const float*)d_in[3];
    const float* W2 = (const float*)d_in[4];
    const float* b2 = (const float*)d_in[5];
    float* out = (float*)d_out;
    int E = in_sizes[1] / 2;
    if (E > EMAX) E = EMAX;  // safety (dataset E = 1.6M)

    k_deg<<<(E + 255) / 256, 256>>>(ei, E);            // 0
    k_rowp<<<(NN + 255) / 256, 256>>>();               // 1
    k_fill<<<(E + 255) / 256, 256>>>(ei, E);           // 2
    k_gemm1<<<(NN + 63) / 64, 128>>>(x, W1);           // 3 <- ncu window
    k_agg1<<<(NN + 7) / 8, 256>>>(b1);                 // 4
    k_gemm2<<<(NN + 63) / 64, 160>>>(W2);              // 5
    k_agg2<<<(NN * 10 + 319) / 320, 320>>>(b2);        // 6
    k_lsm<<<(NN + 7) / 8, 256>>>(out);                 // 7
}

// round 8
// speedup vs baseline: 1.1029x; 1.1029x over previous
#include <cuda_runtime.h>
#include <math_constants.h>

#define NN 100000
#define FI 256
#define FH 128
#define FO 40
#define EMAX 1700000

typedef unsigned long long u64;

// ---------------- scratch (static device globals; zero-init at load) --------
__device__ int   g_cnt[NN];        // degree counts (restored to 0 each call)
__device__ int   g_rowp[NN];       // CSR row start
__device__ int   g_cur[NN];        // fill cursor; after fill == row end
__device__ int   g_nbr[EMAX];      // CSR neighbor (src) ids
__device__ int   g_alloc;          // row allocation cursor
__device__ __align__(256) float g_dinv[NN];
__device__ __align__(256) float g_h1[NN * FH];
__device__ __align__(256) float g_agg1[NN * FH];
__device__ __align__(256) float g_h2[NN * FO];
__device__ __align__(256) float g_agg2[NN * FO];

// ---------------- packed fp32x2 helpers -------------------------------------
__device__ __forceinline__ u64 pack2(float lo, float hi) {
    u64 r; asm("mov.b64 %0, {%1, %2};" : "=l"(r) : "f"(lo), "f"(hi)); return r;
}
__device__ __forceinline__ float2 unpack2(u64 v) {
    float2 f; asm("mov.b64 {%0, %1}, %2;" : "=f"(f.x), "=f"(f.y) : "l"(v)); return f;
}
__device__ __forceinline__ u64 ffma2(u64 a, u64 b, u64 c) {
    u64 d; asm("fma.rn.f32x2 %0, %1, %2, %3;" : "=l"(d) : "l"(a), "l"(b), "l"(c)); return d;
}
__device__ __forceinline__ void cp16(void* smem_dst, const void* gmem_src) {
    unsigned s = (unsigned)__cvta_generic_to_shared(smem_dst);
    asm volatile("cp.async.cg.shared.global [%0], [%1], 16;" :: "r"(s), "l"(gmem_src));
}
__device__ __forceinline__ void cp_commit() { asm volatile("cp.async.commit_group;"); }
__device__ __forceinline__ void cp_wait0()  { asm volatile("cp.async.wait_group 0;"); }

// dtype probe: int32 data viewed as int64 has random hi-words -> out of range.
__device__ __forceinline__ int probe64(const void* ei) {
    const long long* p = (const long long*)ei;
    int ok = 1;
    #pragma unroll
    for (int j = 0; j < 8; j++) {
        long long v = p[j];
        if (v < 0 || v >= NN) ok = 0;
    }
    return ok;
}
__device__ __forceinline__ int eidx(const void* p, long long i, int is64) {
    if (is64) return (int)((const long long*)p)[i];
    return ((const int*)p)[i];
}

// ---------------- CSR build --------------------------------------------------
__global__ void k_deg(const void* ei, int E) {
    int i = blockIdx.x * blockDim.x + threadIdx.x;
    if (i == 0) g_alloc = 0;
    int is64 = probe64(ei);
    if (i < E) {
        int d = eidx(ei, (long long)E + i, is64);
        atomicAdd(&g_cnt[d], 1);
    }
}

__global__ void k_rowp() {
    int i = blockIdx.x * blockDim.x + threadIdx.x;
    if (i < NN) {
        int c = g_cnt[i];
        int start = atomicAdd(&g_alloc, c);
        g_rowp[i] = start;
        g_cur[i]  = start;
        g_dinv[i] = rsqrtf((float)c + 1.0f);
        g_cnt[i]  = 0;
    }
}

__global__ void k_fill(const void* ei, int E) {
    int i = blockIdx.x * blockDim.x + threadIdx.x;
    int is64 = probe64(ei);
    if (i < E) {
        int s = eidx(ei, i, is64);
        int d = eidx(ei, (long long)E + i, is64);
        int p = atomicAdd(&g_cur[d], 1);
        g_nbr[p] = s;
    }
}

// ---------------- GEMM1: h1 = x @ W1  (100000x256 @ 256x128) ----------------
// R6 tile (256 thr, 8 warps x 16 rows, 2 colpairs/lane, 128 rows/CTA) plus
// double-buffered smem pipeline: W via cp.async (layout bit-identical to
// global float2), X via LDG.128 reg-prefetch + dup-pack STS after compute.
// Dyn smem 96 KB: Wbuf[2][2048] u64, Xbuf[2][2048] u64.
__global__ void __launch_bounds__(256, 2) k_gemm1(const float* __restrict__ x,
                                                  const float* __restrict__ W1) {
    extern __shared__ u64 dyn[];
    u64* Wbuf = dyn;          // 2 * 2048
    u64* Xbuf = dyn + 4096;   // 2 * 2048
    int t = threadIdx.x;
    int tx = t & 31, tg = t >> 5;
    int row0 = blockIdx.x * 128;

    // per-thread X prefetch coords: 4 float4 per chunk
    int xr[4], xq[4];
    #pragma unroll
    for (int j = 0; j < 4; j++) {
        int i4 = t + 256 * j;          // 1024 float4 per chunk
        int r = i4 >> 3;               // 8 float4 per row
        xq[j] = i4 & 7;
        int row = row0 + r; if (row >= NN) row = NN - 1;
        xr[j] = row;
    }

    u64 acc[2][16];
    #pragma unroll
    for (int c = 0; c < 2; c++)
        #pragma unroll
        for (int r = 0; r < 16; r++) acc[c][r] = 0ULL;

    // ---- prologue: fetch chunk 0 ----
    float4 xv4[4];
    {
        const float4* Wg = (const float4*)W1;   // chunk kt: 1024 x 16B
        #pragma unroll
        for (int j = 0; j < 4; j++) {
            int u = t + 256 * j;
            cp16(&Wbuf[2 * u], &Wg[u]);
        }
        cp_commit();
        #pragma unroll
        for (int j = 0; j < 4; j++)
            xv4[j] = *(const float4*)(x + (size_t)xr[j] * FI + xq[j] * 4);
        cp_wait0();
        #pragma unroll
        for (int j = 0; j < 4; j++) {
            int i4 = t + 256 * j;
            int r = i4 >> 3;
            u64* dst = &Xbuf[r * 32 + xq[j] * 4];
            ((ulonglong2*)dst)[0] = make_ulonglong2(pack2(xv4[j].x, xv4[j].x), pack2(xv4[j].y, xv4[j].y));
            ((ulonglong2*)dst)[1] = make_ulonglong2(pack2(xv4[j].z, xv4[j].z), pack2(xv4[j].w, xv4[j].w));
        }
    }
    __syncthreads();

    for (int kt = 0; kt < 8; kt++) {
        int cur = kt & 1, nxt = cur ^ 1;
        u64* Ws2 = Wbuf + cur * 2048;
        u64* Xs2 = Xbuf + cur * 2048;

        if (kt < 7) {
            const float4* Wg = (const float4*)(W1 + (size_t)((kt + 1) * 32) * 128);
            #pragma unroll
            for (int j = 0; j < 4; j++) {
                int u = t + 256 * j;
                cp16(&Wbuf[nxt * 2048 + 2 * u], &Wg[u]);
            }
            cp_commit();
            const float* xb = x + (kt + 1) * 32;
            #pragma unroll
            for (int j = 0; j < 4; j++)
                xv4[j] = *(const float4*)(xb + (size_t)xr[j] * FI + xq[j] * 4);
        }

        #pragma unroll
        for (int k = 0; k < 32; k += 2) {
            u64 w00 = Ws2[k * 64 + tx];
            u64 w01 = Ws2[k * 64 + tx + 32];
            u64 w10 = Ws2[(k + 1) * 64 + tx];
            u64 w11 = Ws2[(k + 1) * 64 + tx + 32];
            #pragma unroll
            for (int r = 0; r < 16; r++) {
                ulonglong2 xv = *(const ulonglong2*)&Xs2[(tg * 16 + r) * 32 + k];
                acc[0][r] = ffma2(xv.x, w00, acc[0][r]);
                acc[1][r] = ffma2(xv.x, w01, acc[1][r]);
                acc[0][r] = ffma2(xv.y, w10, acc[0][r]);
                acc[1][r] = ffma2(xv.y, w11, acc[1][r]);
            }
        }

        if (kt < 7) {
            cp_wait0();
            #pragma unroll
            for (int j = 0; j < 4; j++) {
                int i4 = t + 256 * j;
                int r = i4 >> 3;
                u64* dst = &Xbuf[nxt * 2048 + r * 32 + xq[j] * 4];
                ((ulonglong2*)dst)[0] = make_ulonglong2(pack2(xv4[j].x, xv4[j].x), pack2(xv4[j].y, xv4[j].y));
                ((ulonglong2*)dst)[1] = make_ulonglong2(pack2(xv4[j].z, xv4[j].z), pack2(xv4[j].w, xv4[j].w));
            }
        }
        __syncthreads();
    }

    #pragma unroll
    for (int r = 0; r < 16; r++) {
        int row = row0 + tg * 16 + r;
        if (row < NN) {
            #pragma unroll
            for (int c = 0; c < 2; c++) {
                ((float2*)g_h1)[(size_t)row * 64 + tx + c * 32] = unpack2(acc[c][r]);
            }
        }
    }
}

// ---------------- layer-1 aggregate: warp-per-dst CSR gather -----------------
__global__ void __launch_bounds__(256) k_agg1(const float* __restrict__ b1) {
    int w = (blockIdx.x * 256 + threadIdx.x) >> 5;
    int lane = threadIdx.x & 31;
    if (w >= NN) return;
    int e = g_rowp[w], end = g_cur[w];
    float did = g_dinv[w];
    const float4* H = (const float4*)g_h1;

    float4 acc = ((const float4*)b1)[lane];
    float4 self = H[(size_t)w * 32 + lane];
    float d2 = did * did;
    acc.x = fmaf(self.x, d2, acc.x);
    acc.y = fmaf(self.y, d2, acc.y);
    acc.z = fmaf(self.z, d2, acc.z);
    acc.w = fmaf(self.w, d2, acc.w);

    int s = (e < end) ? g_nbr[e] : 0;
    while (e < end) {
        int sn = (e + 1 < end) ? g_nbr[e + 1] : 0;
        float nm = did * g_dinv[s];
        float4 v = H[(size_t)s * 32 + lane];
        acc.x = fmaf(v.x, nm, acc.x);
        acc.y = fmaf(v.y, nm, acc.y);
        acc.z = fmaf(v.z, nm, acc.z);
        acc.w = fmaf(v.w, nm, acc.w);
        s = sn;
        e++;
    }
    ((float4*)g_agg1)[(size_t)w * 32 + lane] = acc;
}

// ---------------- GEMM2: h2 = relu(agg1) @ W2  (100000x128 @ 128x40) --------
__global__ void __launch_bounds__(160) k_gemm2(const float* __restrict__ W2) {
    __shared__ u64 Ws2[64 * 20];   // 10 KB
    __shared__ u64 Xs2[64 * 64];   // 32 KB
    int t = threadIdx.x;
    int tx = t % 20, tg = t / 20;
    int row0 = blockIdx.x * 64;

    u64 acc[8];
    #pragma unroll
    for (int r = 0; r < 8; r++) acc[r] = 0ULL;

    for (int kt = 0; kt < 2; kt++) {
        const float2* Wg = (const float2*)(W2 + (size_t)(kt * 64) * 40);
        for (int i = t; i < 1280; i += 160) {
            float2 w = Wg[i];
            Ws2[i] = pack2(w.x, w.y);
        }
        for (int i = t; i < 4096; i += 160) {
            int r = i >> 6, k = i & 63;
            int row = row0 + r; if (row >= NN) row = NN - 1;
            float v = fmaxf(g_agg1[(size_t)row * FH + kt * 64 + k], 0.f);
            Xs2[i] = pack2(v, v);
        }
        __syncthreads();

        #pragma unroll
        for (int k = 0; k < 64; k += 2) {
            u64 w0 = Ws2[k * 20 + tx];
            u64 w1 = Ws2[(k + 1) * 20 + tx];
            #pragma unroll
            for (int r = 0; r < 8; r++) {
                ulonglong2 xv = *(const ulonglong2*)&Xs2[(tg * 8 + r) * 64 + k];
                acc[r] = ffma2(xv.x, w0, acc[r]);
                acc[r] = ffma2(xv.y, w1, acc[r]);
            }
        }
        __syncthreads();
    }

    #pragma unroll
    for (int r = 0; r < 8; r++) {
        int row = row0 + tg * 8 + r;
        if (row < NN)
            ((float2*)g_h2)[(size_t)row * 20 + tx] = unpack2(acc[r]);
    }
}

// ---------------- layer-2 aggregate: 10-threads-per-dst CSR gather -----------
__global__ void __launch_bounds__(320) k_agg2(const float* __restrict__ b2) {
    int idx = blockIdx.x * 320 + threadIdx.x;
    int w = idx / 10, c = idx % 10;
    if (w >= NN) return;
    int e = g_rowp[w], end = g_cur[w];
    float did = g_dinv[w];
    const float4* H = (const float4*)g_h2;

    float4 acc = ((const float4*)b2)[c];
    float4 self = H[(size_t)w * 10 + c];
    float d2 = did * did;
    acc.x = fmaf(self.x, d2, acc.x);
    acc.y = fmaf(self.y, d2, acc.y);
    acc.z = fmaf(self.z, d2, acc.z);
    acc.w = fmaf(self.w, d2, acc.w);

    int s = (e < end) ? g_nbr[e] : 0;
    while (e < end) {
        int sn = (e + 1 < end) ? g_nbr[e + 1] : 0;
        float nm = did * g_dinv[s];
        float4 v = H[(size_t)s * 10 + c];
        acc.x = fmaf(v.x, nm, acc.x);
        acc.y = fmaf(v.y, nm, acc.y);
        acc.z = fmaf(v.z, nm, acc.z);
        acc.w = fmaf(v.w, nm, acc.w);
        s = sn;
        e++;
    }
    ((float4*)g_agg2)[(size_t)w * 10 + c] = acc;
}

// ---------------- log_softmax, warp per row ----------------------------------
__global__ void k_lsm(float* __restrict__ out) {
    int row = (blockIdx.x * blockDim.x + threadIdx.x) >> 5;
    int lane = threadIdx.x & 31;
    if (row < NN) {
        const float* in = g_agg2 + (size_t)row * FO;
        float v0 = in[lane];
        float v1 = (lane < 8) ? in[32 + lane] : -CUDART_INF_F;
        float m = fmaxf(v0, v1);
        #pragma unroll
        for (int o = 16; o; o >>= 1) m = fmaxf(m, __shfl_xor_sync(0xffffffffu, m, o));
        float s = expf(v0 - m) + ((lane < 8) ? expf(v1 - m) : 0.f);
        #pragma unroll
        for (int o = 16; o; o >>= 1) s += __shfl_xor_sync(0xffffffffu, s, o);
        float ls = m + logf(s);
        out[(size_t)row * FO + lane] = v0 - ls;
        if (lane < 8) out[(size_t)row * FO + 32 + lane] = v1 - ls;
    }
}

// ---------------- launch ------------------------------------------------------
extern "C" void kernel_launch(void* const* d_in, const int* in_sizes, int n_in,
                              void* d_out, int out_size) {
    const float* x  = (const float*)d_in[0];
    const void*  ei = d_in[1];
    const float* W1 = (const float*)d_in[2];
    const float* b1 = (const float*)d_in[3];
    const float* W2 = (const float*)d_in[4];
    const float* b2 = (const float*)d_in[5];
    float* out = (float*)d_out;
    int E = in_sizes[1] / 2;
    if (E > EMAX) E = EMAX;

    static int smem_set = 0;
    if (!smem_set) {
        cudaFuncSetAttribute(k_gemm1, cudaFuncAttributeMaxDynamicSharedMemorySize, 98304);
        smem_set = 1;
    }

    k_deg<<<(E + 255) / 256, 256>>>(ei, E);                 // 0
    k_rowp<<<(NN + 255) / 256, 256>>>();                    // 1
    k_fill<<<(E + 255) / 256, 256>>>(ei, E);                // 2
    k_gemm1<<<(NN + 127) / 128, 256, 98304>>>(x, W1);       // 3 <- ncu window
    k_agg1<<<(NN + 7) / 8, 256>>>(b1);                      // 4
    k_gemm2<<<(NN + 63) / 64, 160>>>(W2);                   // 5
    k_agg2<<<(NN * 10 + 319) / 320, 320>>>(b2);             // 6
    k_lsm<<<(NN + 7) / 8, 256>>>(out);                      // 7
}

// round 9
// speedup vs baseline: 1.3117x; 1.1893x over previous
#include <cuda_runtime.h>
#include <math_constants.h>

#define NN 100000
#define FI 256
#define FH 128
#define FO 40
#define EMAX 1700000

typedef unsigned long long u64;
typedef unsigned int u32;

// ---------------- scratch (static device globals; zero-init at load) --------
__device__ int   g_cnt[NN];
__device__ int   g_rowp[NN];
__device__ int   g_cur[NN];
__device__ int   g_nbr[EMAX];
__device__ int   g_alloc;
__device__ __align__(256) float g_dinv[NN];
__device__ __align__(256) float g_h1[NN * FH];
__device__ __align__(256) float g_agg1[NN * FH];
__device__ __align__(256) float g_h2[NN * FO];
__device__ __align__(256) float g_agg2[NN * FO];

// ---------------- helpers ----------------------------------------------------
__device__ __forceinline__ u64 pack2(float lo, float hi) {
    u64 r; asm("mov.b64 %0, {%1, %2};" : "=l"(r) : "f"(lo), "f"(hi)); return r;
}
__device__ __forceinline__ float2 unpack2(u64 v) {
    float2 f; asm("mov.b64 {%0, %1}, %2;" : "=f"(f.x), "=f"(f.y) : "l"(v)); return f;
}
__device__ __forceinline__ u64 ffma2(u64 a, u64 b, u64 c) {
    u64 d; asm("fma.rn.f32x2 %0, %1, %2, %3;" : "=l"(d) : "l"(a), "l"(b), "l"(c)); return d;
}
// pack two floats to bf16x2: lo_elem -> low 16 bits, hi_elem -> high 16 bits
__device__ __forceinline__ u32 bfpack(float lo_elem, float hi_elem) {
    u32 r; asm("cvt.rn.bf16x2.f32 %0, %1, %2;" : "=r"(r) : "f"(hi_elem), "f"(lo_elem));
    return r;
}
__device__ __forceinline__ float bf_lo_f32(u32 p) { return __uint_as_float(p << 16); }
__device__ __forceinline__ float bf_hi_f32(u32 p) { return __uint_as_float(p & 0xffff0000u); }

__device__ __forceinline__ void mma_bf16(float* d, const u32* a, u32 b0, u32 b1) {
    asm("mma.sync.aligned.m16n8k16.row.col.f32.bf16.bf16.f32 "
        "{%0,%1,%2,%3}, {%4,%5,%6,%7}, {%8,%9}, {%0,%1,%2,%3};"
        : "+f"(d[0]), "+f"(d[1]), "+f"(d[2]), "+f"(d[3])
        : "r"(a[0]), "r"(a[1]), "r"(a[2]), "r"(a[3]), "r"(b0), "r"(b1));
}

__device__ __forceinline__ int probe64(const void* ei) {
    const long long* p = (const long long*)ei;
    int ok = 1;
    #pragma unroll
    for (int j = 0; j < 8; j++) {
        long long v = p[j];
        if (v < 0 || v >= NN) ok = 0;
    }
    return ok;
}
__device__ __forceinline__ int eidx(const void* p, long long i, int is64) {
    if (is64) return (int)((const long long*)p)[i];
    return ((const int*)p)[i];
}

// ---------------- CSR build --------------------------------------------------
__global__ void k_deg(const void* ei, int E) {
    int i = blockIdx.x * blockDim.x + threadIdx.x;
    if (i == 0) g_alloc = 0;
    int is64 = probe64(ei);
    if (i < E) {
        int d = eidx(ei, (long long)E + i, is64);
        atomicAdd(&g_cnt[d], 1);
    }
}
__global__ void k_rowp() {
    int i = blockIdx.x * blockDim.x + threadIdx.x;
    if (i < NN) {
        int c = g_cnt[i];
        int start = atomicAdd(&g_alloc, c);
        g_rowp[i] = start;
        g_cur[i]  = start;
        g_dinv[i] = rsqrtf((float)c + 1.0f);
        g_cnt[i]  = 0;
    }
}
__global__ void k_fill(const void* ei, int E) {
    int i = blockIdx.x * blockDim.x + threadIdx.x;
    int is64 = probe64(ei);
    if (i < E) {
        int s = eidx(ei, i, is64);
        int d = eidx(ei, (long long)E + i, is64);
        int p = atomicAdd(&g_cur[d], 1);
        g_nbr[p] = s;
    }
}

// ---------------- GEMM1 via tensor cores: h1 = x @ W1 ------------------------
// bf16 2-term split (hi+lo), 3 products: hi*hi + hi*lo + lo*hi.
// CTA: 256 thr (8 warps), tile 128 rows x 128 cols. Warp: wr=wid&3 (m=wr*32),
// wc=wid>>2 (n=wc*64). K chunked by 64 (4 chunks), mma m16n8k16.
// smem (u32, dynamic 70KB):
//   Ah/Al:  [128][36]  u32 per row = 32 k-pairs + pad4 (bank 4r+c, conflict-free)
//   Bph/Bpl:[32][136]  Bp[k2][n] = pack(W[2k2][n], W[2k2+1][n]), pad for 8m+q banks
#define A_STR 36
#define B_STR 136
#define SM_AH 0
#define SM_AL (128 * A_STR)
#define SM_BH (2 * 128 * A_STR)
#define SM_BL (2 * 128 * A_STR + 32 * B_STR)
#define SM_TOT (2 * 128 * A_STR + 2 * 32 * B_STR)   // 17920 u32 = 71680 B

__global__ void __launch_bounds__(256) k_gemm1(const float* __restrict__ x,
                                               const float* __restrict__ W1) {
    extern __shared__ u32 sm[];
    int t = threadIdx.x;
    int lane = t & 31, wid = t >> 5;
    int g = lane >> 2, t4 = lane & 3;
    int wr = wid & 3, wc = wid >> 2;
    int row0 = blockIdx.x * 128;

    float d[2][8][4];
    #pragma unroll
    for (int mt = 0; mt < 2; mt++)
        #pragma unroll
        for (int j = 0; j < 8; j++)
            #pragma unroll
            for (int q = 0; q < 4; q++) d[mt][j][q] = 0.f;

    for (int ct = 0; ct < 4; ct++) {
        // ---- load X chunk: 128 rows x 64 k -> Ah/Al ----
        #pragma unroll
        for (int jj = 0; jj < 8; jj++) {
            int i4 = t + 256 * jj;           // 2048 float4
            int r = i4 >> 4, q = i4 & 15;    // 16 float4 per row
            int row = row0 + r; if (row >= NN) row = NN - 1;
            float4 v = *(const float4*)(x + (size_t)row * FI + ct * 64 + q * 4);
            u32 h0 = bfpack(v.x, v.y);
            u32 h1 = bfpack(v.z, v.w);
            u32 l0 = bfpack(v.x - bf_lo_f32(h0), v.y - bf_hi_f32(h0));
            u32 l1 = bfpack(v.z - bf_lo_f32(h1), v.w - bf_hi_f32(h1));
            sm[SM_AH + r * A_STR + 2 * q]     = h0;
            sm[SM_AH + r * A_STR + 2 * q + 1] = h1;
            sm[SM_AL + r * A_STR + 2 * q]     = l0;
            sm[SM_AL + r * A_STR + 2 * q + 1] = l1;
        }
        // ---- load W chunk: 64 k x 128 n -> Bph/Bpl (k-pair packed) ----
        #pragma unroll
        for (int jj = 0; jj < 4; jj++) {
            int id = t + 256 * jj;           // 1024 tasks
            int k2 = id >> 5, ng = id & 31;  // 4-col group
            const float* wbase = W1 + (size_t)(ct * 64 + 2 * k2) * 128 + ng * 4;
            float4 w0 = *(const float4*)wbase;
            float4 w1 = *(const float4*)(wbase + 128);
            u32 o = k2 * B_STR + ng * 4;
            float a0[4] = {w0.x, w0.y, w0.z, w0.w};
            float a1[4] = {w1.x, w1.y, w1.z, w1.w};
            #pragma unroll
            for (int n = 0; n < 4; n++) {
                u32 h = bfpack(a0[n], a1[n]);          // low=row 2k2, high=row 2k2+1
                u32 l = bfpack(a0[n] - bf_lo_f32(h), a1[n] - bf_hi_f32(h));
                sm[SM_BH + o + n] = h;
                sm[SM_BL + o + n] = l;
            }
        }
        __syncthreads();

        // ---- compute: 4 k16-steps ----
        #pragma unroll
        for (int s = 0; s < 4; s++) {
            u32 ah[2][4], al[2][4];
            #pragma unroll
            for (int mt = 0; mt < 2; mt++) {
                int rb = wr * 32 + mt * 16;
                int ka = s * 8 + t4;
                ah[mt][0] = sm[SM_AH + (rb + g) * A_STR + ka];
                ah[mt][1] = sm[SM_AH + (rb + g + 8) * A_STR + ka];
                ah[mt][2] = sm[SM_AH + (rb + g) * A_STR + ka + 4];
                ah[mt][3] = sm[SM_AH + (rb + g + 8) * A_STR + ka + 4];
                al[mt][0] = sm[SM_AL + (rb + g) * A_STR + ka];
                al[mt][1] = sm[SM_AL + (rb + g + 8) * A_STR + ka];
                al[mt][2] = sm[SM_AL + (rb + g) * A_STR + ka + 4];
                al[mt][3] = sm[SM_AL + (rb + g + 8) * A_STR + ka + 4];
            }
            #pragma unroll
            for (int j = 0; j < 8; j++) {
                int nb = wc * 64 + j * 8 + g;
                int kb = s * 8 + t4;
                u32 bh0 = sm[SM_BH + kb * B_STR + nb];
                u32 bh1 = sm[SM_BH + (kb + 4) * B_STR + nb];
                u32 bl0 = sm[SM_BL + kb * B_STR + nb];
                u32 bl1 = sm[SM_BL + (kb + 4) * B_STR + nb];
                #pragma unroll
                for (int mt = 0; mt < 2; mt++) {
                    mma_bf16(d[mt][j], ah[mt], bh0, bh1);   // hi*hi
                    mma_bf16(d[mt][j], ah[mt], bl0, bl1);   // hi*lo
                    mma_bf16(d[mt][j], al[mt], bh0, bh1);   // lo*hi
                }
            }
        }
        __syncthreads();
    }

    // ---- epilogue: write h1 ----
    #pragma unroll
    for (int mt = 0; mt < 2; mt++) {
        int rbase = row0 + wr * 32 + mt * 16;
        #pragma unroll
        for (int j = 0; j < 8; j++) {
            int cp = wc * 32 + j * 4 + t4;   // float2 column index
            int r0 = rbase + g, r1 = rbase + g + 8;
            if (r0 < NN)
                ((float2*)g_h1)[(size_t)r0 * 64 + cp] = make_float2(d[mt][j][0], d[mt][j][1]);
            if (r1 < NN)
                ((float2*)g_h1)[(size_t)r1 * 64 + cp] = make_float2(d[mt][j][2], d[mt][j][3]);
        }
    }
}

// ---------------- layer-1 aggregate: warp-per-dst CSR gather -----------------
__global__ void __launch_bounds__(256) k_agg1(const float* __restrict__ b1) {
    int w = (blockIdx.x * 256 + threadIdx.x) >> 5;
    int lane = threadIdx.x & 31;
    if (w >= NN) return;
    int e = g_rowp[w], end = g_cur[w];
    float did = g_dinv[w];
    const float4* H = (const float4*)g_h1;

    float4 acc = ((const float4*)b1)[lane];
    float4 self = H[(size_t)w * 32 + lane];
    float d2 = did * did;
    acc.x = fmaf(self.x, d2, acc.x);
    acc.y = fmaf(self.y, d2, acc.y);
    acc.z = fmaf(self.z, d2, acc.z);
    acc.w = fmaf(self.w, d2, acc.w);

    int s = (e < end) ? g_nbr[e] : 0;
    while (e < end) {
        int sn = (e + 1 < end) ? g_nbr[e + 1] : 0;
        float nm = did * g_dinv[s];
        float4 v = H[(size_t)s * 32 + lane];
        acc.x = fmaf(v.x, nm, acc.x);
        acc.y = fmaf(v.y, nm, acc.y);
        acc.z = fmaf(v.z, nm, acc.z);
        acc.w = fmaf(v.w, nm, acc.w);
        s = sn;
        e++;
    }
    ((float4*)g_agg1)[(size_t)w * 32 + lane] = acc;
}

// ---------------- GEMM2: h2 = relu(agg1) @ W2  (100000x128 @ 128x40) --------
__global__ void __launch_bounds__(160) k_gemm2(const float* __restrict__ W2) {
    __shared__ u64 Ws2[64 * 20];
    __shared__ u64 Xs2[64 * 64];
    int t = threadIdx.x;
    int tx = t % 20, tg = t / 20;
    int row0 = blockIdx.x * 64;

    u64 acc[8];
    #pragma unroll
    for (int r = 0; r < 8; r++) acc[r] = 0ULL;

    for (int kt = 0; kt < 2; kt++) {
        const float2* Wg = (const float2*)(W2 + (size_t)(kt * 64) * 40);
        for (int i = t; i < 1280; i += 160) {
            float2 w = Wg[i];
            Ws2[i] = pack2(w.x, w.y);
        }
        for (int i = t; i < 4096; i += 160) {
            int r = i >> 6, k = i & 63;
            int row = row0 + r; if (row >= NN) row = NN - 1;
            float v = fmaxf(g_agg1[(size_t)row * FH + kt * 64 + k], 0.f);
            Xs2[i] = pack2(v, v);
        }
        __syncthreads();

        #pragma unroll
        for (int k = 0; k < 64; k += 2) {
            u64 w0 = Ws2[k * 20 + tx];
            u64 w1 = Ws2[(k + 1) * 20 + tx];
            #pragma unroll
            for (int r = 0; r < 8; r++) {
                ulonglong2 xv = *(const ulonglong2*)&Xs2[(tg * 8 + r) * 64 + k];
                acc[r] = ffma2(xv.x, w0, acc[r]);
                acc[r] = ffma2(xv.y, w1, acc[r]);
            }
        }
        __syncthreads();
    }

    #pragma unroll
    for (int r = 0; r < 8; r++) {
        int row = row0 + tg * 8 + r;
        if (row < NN)
            ((float2*)g_h2)[(size_t)row * 20 + tx] = unpack2(acc[r]);
    }
}

// ---------------- layer-2 aggregate: 10-threads-per-dst CSR gather -----------
__global__ void __launch_bounds__(320) k_agg2(const float* __restrict__ b2) {
    int idx = blockIdx.x * 320 + threadIdx.x;
    int w = idx / 10, c = idx % 10;
    if (w >= NN) return;
    int e = g_rowp[w], end = g_cur[w];
    float did = g_dinv[w];
    const float4* H = (const float4*)g_h2;

    float4 acc = ((const float4*)b2)[c];
    float4 self = H[(size_t)w * 10 + c];
    float d2 = did * did;
    acc.x = fmaf(self.x, d2, acc.x);
    acc.y = fmaf(self.y, d2, acc.y);
    acc.z = fmaf(self.z, d2, acc.z);
    acc.w = fmaf(self.w, d2, acc.w);

    int s = (e < end) ? g_nbr[e] : 0;
    while (e < end) {
        int sn = (e + 1 < end) ? g_nbr[e + 1] : 0;
        float nm = did * g_dinv[s];
        float4 v = H[(size_t)s * 10 + c];
        acc.x = fmaf(v.x, nm, acc.x);
        acc.y = fmaf(v.y, nm, acc.y);
        acc.z = fmaf(v.z, nm, acc.z);
        acc.w = fmaf(v.w, nm, acc.w);
        s = sn;
        e++;
    }
    ((float4*)g_agg2)[(size_t)w * 10 + c] = acc;
}

// ---------------- log_softmax, warp per row ----------------------------------
__global__ void k_lsm(float* __restrict__ out) {
    int row = (blockIdx.x * blockDim.x + threadIdx.x) >> 5;
    int lane = threadIdx.x & 31;
    if (row < NN) {
        const float* in = g_agg2 + (size_t)row * FO;
        float v0 = in[lane];
        float v1 = (lane < 8) ? in[32 + lane] : -CUDART_INF_F;
        float m = fmaxf(v0, v1);
        #pragma unroll
        for (int o = 16; o; o >>= 1) m = fmaxf(m, __shfl_xor_sync(0xffffffffu, m, o));
        float s = expf(v0 - m) + ((lane < 8) ? expf(v1 - m) : 0.f);
        #pragma unroll
        for (int o = 16; o; o >>= 1) s += __shfl_xor_sync(0xffffffffu, s, o);
        float ls = m + logf(s);
        out[(size_t)row * FO + lane] = v0 - ls;
        if (lane < 8) out[(size_t)row * FO + 32 + lane] = v1 - ls;
    }
}

// ---------------- launch ------------------------------------------------------
extern "C" void kernel_launch(void* const* d_in, const int* in_sizes, int n_in,
                              void* d_out, int out_size) {
    const float* x  = (const float*)d_in[0];
    const void*  ei = d_in[1];
    const float* W1 = (const float*)d_in[2];
    const float* b1 = (const float*)d_in[3];
    const float* W2 = (const float*)d_in[4];
    const float* b2 = (const float*)d_in[5];
    float* out = (float*)d_out;
    int E = in_sizes[1] / 2;
    if (E > EMAX) E = EMAX;

    static int smem_set = 0;
    if (!smem_set) {
        cudaFuncSetAttribute(k_gemm1, cudaFuncAttributeMaxDynamicSharedMemorySize,
                             SM_TOT * 4);
        smem_set = 1;
    }

    k_deg<<<(E + 255) / 256, 256>>>(ei, E);                   // 0
    k_rowp<<<(NN + 255) / 256, 256>>>();                      // 1
    k_fill<<<(E + 255) / 256, 256>>>(ei, E);                  // 2
    k_gemm1<<<(NN + 127) / 128, 256, SM_TOT * 4>>>(x, W1);    // 3 <- ncu window
    k_agg1<<<(NN + 7) / 8, 256>>>(b1);                        // 4
    k_gemm2<<<(NN + 63) / 64, 160>>>(W2);                     // 5
    k_agg2<<<(NN * 10 + 319) / 320, 320>>>(b2);               // 6
    k_lsm<<<(NN + 7) / 8, 256>>>(out);                        // 7
}

// round 10
// speedup vs baseline: 1.4387x; 1.0969x over previous
#include <cuda_runtime.h>
#include <math_constants.h>

#define NN 100000
#define FI 256
#define FH 128
#define FO 40
#define EMAX 1700000

typedef unsigned long long u64;
typedef unsigned int u32;

// ---------------- scratch (static device globals; zero-init at load) --------
__device__ int   g_cnt[NN];
__device__ int   g_rowp[NN];
__device__ int   g_cur[NN];
__device__ int   g_nbr[EMAX];
__device__ int   g_alloc;
__device__ __align__(256) float g_dinv[NN];
__device__ __align__(256) u32   g_w1h[128 * 128];  // W1 split: hi bf16x2, [k2][n]
__device__ __align__(256) u32   g_w1l[128 * 128];  // W1 split: lo bf16x2
__device__ __align__(256) float g_h1[NN * FH];
__device__ __align__(256) float g_agg1[NN * FH];
__device__ __align__(256) float g_h2[NN * FO];
__device__ __align__(256) float g_agg2[NN * FO];

// ---------------- helpers ----------------------------------------------------
__device__ __forceinline__ u64 pack2(float lo, float hi) {
    u64 r; asm("mov.b64 %0, {%1, %2};" : "=l"(r) : "f"(lo), "f"(hi)); return r;
}
__device__ __forceinline__ float2 unpack2(u64 v) {
    float2 f; asm("mov.b64 {%0, %1}, %2;" : "=f"(f.x), "=f"(f.y) : "l"(v)); return f;
}
__device__ __forceinline__ u64 ffma2(u64 a, u64 b, u64 c) {
    u64 d; asm("fma.rn.f32x2 %0, %1, %2, %3;" : "=l"(d) : "l"(a), "l"(b), "l"(c)); return d;
}
__device__ __forceinline__ u32 bfpack(float lo_elem, float hi_elem) {
    u32 r; asm("cvt.rn.bf16x2.f32 %0, %1, %2;" : "=r"(r) : "f"(hi_elem), "f"(lo_elem));
    return r;
}
__device__ __forceinline__ float bf_lo_f32(u32 p) { return __uint_as_float(p << 16); }
__device__ __forceinline__ float bf_hi_f32(u32 p) { return __uint_as_float(p & 0xffff0000u); }

__device__ __forceinline__ void mma_bf16(float* d, const u32* a, u32 b0, u32 b1) {
    asm("mma.sync.aligned.m16n8k16.row.col.f32.bf16.bf16.f32 "
        "{%0,%1,%2,%3}, {%4,%5,%6,%7}, {%8,%9}, {%0,%1,%2,%3};"
        : "+f"(d[0]), "+f"(d[1]), "+f"(d[2]), "+f"(d[3])
        : "r"(a[0]), "r"(a[1]), "r"(a[2]), "r"(a[3]), "r"(b0), "r"(b1));
}
__device__ __forceinline__ void cp16(void* smem_dst, const void* gmem_src) {
    unsigned s = (unsigned)__cvta_generic_to_shared(smem_dst);
    asm volatile("cp.async.cg.shared.global [%0], [%1], 16;" :: "r"(s), "l"(gmem_src));
}
__device__ __forceinline__ void cp_commit() { asm volatile("cp.async.commit_group;"); }
__device__ __forceinline__ void cp_wait0()  { asm volatile("cp.async.wait_group 0;"); }

__device__ __forceinline__ int probe64(const void* ei) {
    const long long* p = (const long long*)ei;
    int ok = 1;
    #pragma unroll
    for (int j = 0; j < 8; j++) {
        long long v = p[j];
        if (v < 0 || v >= NN) ok = 0;
    }
    return ok;
}
__device__ __forceinline__ int eidx(const void* p, long long i, int is64) {
    if (is64) return (int)((const long long*)p)[i];
    return ((const int*)p)[i];
}

// ---------------- CSR build --------------------------------------------------
__global__ void k_deg(const void* ei, int E) {
    int i = blockIdx.x * blockDim.x + threadIdx.x;
    if (i == 0) g_alloc = 0;
    int is64 = probe64(ei);
    if (i < E) {
        int d = eidx(ei, (long long)E + i, is64);
        atomicAdd(&g_cnt[d], 1);
    }
}
// k_rowp also pre-splits W1 into bf16 hi/lo planes (threads < 16384)
__global__ void k_rowp(const float* __restrict__ W1) {
    int i = blockIdx.x * blockDim.x + threadIdx.x;
    if (i < 16384) {
        int k2 = i >> 7, n = i & 127;
        float w0 = W1[(2 * k2) * 128 + n];
        float w1 = W1[(2 * k2 + 1) * 128 + n];
        u32 h = bfpack(w0, w1);
        u32 l = bfpack(w0 - bf_lo_f32(h), w1 - bf_hi_f32(h));
        g_w1h[i] = h;
        g_w1l[i] = l;
    }
    if (i < NN) {
        int c = g_cnt[i];
        int start = atomicAdd(&g_alloc, c);
        g_rowp[i] = start;
        g_cur[i]  = start;
        g_dinv[i] = rsqrtf((float)c + 1.0f);
        g_cnt[i]  = 0;
    }
}
__global__ void k_fill(const void* ei, int E) {
    int i = blockIdx.x * blockDim.x + threadIdx.x;
    int is64 = probe64(ei);
    if (i < E) {
        int s = eidx(ei, i, is64);
        int d = eidx(ei, (long long)E + i, is64);
        int p = atomicAdd(&g_cur[d], 1);
        g_nbr[p] = s;
    }
}

// ---------------- GEMM1 via tensor cores: h1 = x @ W1 ------------------------
// bf16 2-term split, 3 products. 512 thr (16 warps), tile 128m x 128n.
// Warp: wr=wid&3 -> m=wr*32; wc=wid>>2 -> n=wc*32 (warp tile 32x32).
// K chunks of 64 (4 chunks), double-buffered smem:
//   per buffer (u32): Ah[128][36], Al[128][36], Bh[32][136], Bl[32][136]
// W arrives pre-split via cp.async from g_w1h/g_w1l; X via LDG reg-prefetch.
#define A_STR 36
#define B_STR 136
#define OF_AH 0
#define OF_AL (128 * A_STR)
#define OF_BH (2 * 128 * A_STR)
#define OF_BL (2 * 128 * A_STR + 32 * B_STR)
#define TOT1  (2 * 128 * A_STR + 2 * 32 * B_STR)   // 17920 u32 = 71680 B / buffer

__global__ void __launch_bounds__(512) k_gemm1(const float* __restrict__ x,
                                               const float* __restrict__ W1) {
    extern __shared__ u32 sm[];
    int t = threadIdx.x;
    int lane = t & 31, wid = t >> 5;
    int g = lane >> 2, t4 = lane & 3;
    int wr = wid & 3, wc = wid >> 2;
    int row0 = blockIdx.x * 128;

    // X prefetch coords: 4 float4 per chunk per thread
    int xr[4], xq[4];
    #pragma unroll
    for (int j = 0; j < 4; j++) {
        int i4 = t + 512 * j;            // 2048 float4 per chunk
        int r = i4 >> 4;                 // 16 float4 per row
        xq[j] = i4 & 15;
        int row = row0 + r; if (row >= NN) row = NN - 1;
        xr[j] = row;
    }

    float d[2][4][4];
    #pragma unroll
    for (int mt = 0; mt < 2; mt++)
        #pragma unroll
        for (int j = 0; j < 4; j++)
            #pragma unroll
            for (int q = 0; q < 4; q++) d[mt][j][q] = 0.f;

    float4 xv4[4];
    // ---- prologue: chunk 0 ----
    {
        #pragma unroll
        for (int jj = 0; jj < 2; jj++) {
            int id = t + 512 * jj;       // 1024 tasks
            int k2 = id >> 5, ng = id & 31;
            cp16(&sm[OF_BH + k2 * B_STR + ng * 4], &g_w1h[k2 * 128 + ng * 4]);
            cp16(&sm[OF_BL + k2 * B_STR + ng * 4], &g_w1l[k2 * 128 + ng * 4]);
        }
        cp_commit();
        #pragma unroll
        for (int j = 0; j < 4; j++)
            xv4[j] = *(const float4*)(x + (size_t)xr[j] * FI + xq[j] * 4);
        cp_wait0();
        #pragma unroll
        for (int j = 0; j < 4; j++) {
            int i4 = t + 512 * j;
            int r = i4 >> 4, q = i4 & 15;
            float4 v = xv4[j];
            u32 h0 = bfpack(v.x, v.y);
            u32 h1 = bfpack(v.z, v.w);
            u32 l0 = bfpack(v.x - bf_lo_f32(h0), v.y - bf_hi_f32(h0));
            u32 l1 = bfpack(v.z - bf_lo_f32(h1), v.w - bf_hi_f32(h1));
            sm[OF_AH + r * A_STR + 2 * q]     = h0;
            sm[OF_AH + r * A_STR + 2 * q + 1] = h1;
            sm[OF_AL + r * A_STR + 2 * q]     = l0;
            sm[OF_AL + r * A_STR + 2 * q + 1] = l1;
        }
    }
    __syncthreads();

    for (int ct = 0; ct < 4; ct++) {
        int cur = (ct & 1) * TOT1, nxt = ((ct & 1) ^ 1) * TOT1;

        if (ct < 3) {
            #pragma unroll
            for (int jj = 0; jj < 2; jj++) {
                int id = t + 512 * jj;
                int k2 = id >> 5, ng = id & 31;
                int gofs = (ct + 1) * 4096 + k2 * 128 + ng * 4;
                cp16(&sm[nxt + OF_BH + k2 * B_STR + ng * 4], &g_w1h[gofs]);
                cp16(&sm[nxt + OF_BL + k2 * B_STR + ng * 4], &g_w1l[gofs]);
            }
            cp_commit();
            const float* xb = x + (ct + 1) * 64;
            #pragma unroll
            for (int j = 0; j < 4; j++)
                xv4[j] = *(const float4*)(xb + (size_t)xr[j] * FI + xq[j] * 4);
        }

        // ---- compute chunk ct ----
        #pragma unroll
        for (int s = 0; s < 4; s++) {
            u32 ah[2][4], al[2][4];
            int ka = s * 8 + t4;
            #pragma unroll
            for (int mt = 0; mt < 2; mt++) {
                int rb = wr * 32 + mt * 16;
                ah[mt][0] = sm[cur + OF_AH + (rb + g) * A_STR + ka];
                ah[mt][1] = sm[cur + OF_AH + (rb + g + 8) * A_STR + ka];
                ah[mt][2] = sm[cur + OF_AH + (rb + g) * A_STR + ka + 4];
                ah[mt][3] = sm[cur + OF_AH + (rb + g + 8) * A_STR + ka + 4];
                al[mt][0] = sm[cur + OF_AL + (rb + g) * A_STR + ka];
                al[mt][1] = sm[cur + OF_AL + (rb + g + 8) * A_STR + ka];
                al[mt][2] = sm[cur + OF_AL + (rb + g) * A_STR + ka + 4];
                al[mt][3] = sm[cur + OF_AL + (rb + g + 8) * A_STR + ka + 4];
            }
            #pragma unroll
            for (int j = 0; j < 4; j++) {
                int nb = wc * 32 + j * 8 + g;
                int kb = s * 8 + t4;
                u32 bh0 = sm[cur + OF_BH + kb * B_STR + nb];
                u32 bh1 = sm[cur + OF_BH + (kb + 4) * B_STR + nb];
                u32 bl0 = sm[cur + OF_BL + kb * B_STR + nb];
                u32 bl1 = sm[cur + OF_BL + (kb + 4) * B_STR + nb];
                #pragma unroll
                for (int mt = 0; mt < 2; mt++) {
                    mma_bf16(d[mt][j], ah[mt], bh0, bh1);   // hi*hi
                    mma_bf16(d[mt][j], ah[mt], bl0, bl1);   // hi*lo
                    mma_bf16(d[mt][j], al[mt], bh0, bh1);   // lo*hi
                }
            }
        }

        if (ct < 3) {
            cp_wait0();
            #pragma unroll
            for (int j = 0; j < 4; j++) {
                int i4 = t + 512 * j;
                int r = i4 >> 4, q = i4 & 15;
                float4 v = xv4[j];
                u32 h0 = bfpack(v.x, v.y);
                u32 h1 = bfpack(v.z, v.w);
                u32 l0 = bfpack(v.x - bf_lo_f32(h0), v.y - bf_hi_f32(h0));
                u32 l1 = bfpack(v.z - bf_lo_f32(h1), v.w - bf_hi_f32(h1));
                sm[nxt + OF_AH + r * A_STR + 2 * q]     = h0;
                sm[nxt + OF_AH + r * A_STR + 2 * q + 1] = h1;
                sm[nxt + OF_AL + r * A_STR + 2 * q]     = l0;
                sm[nxt + OF_AL + r * A_STR + 2 * q + 1] = l1;
            }
        }
        __syncthreads();
    }

    // ---- epilogue ----
    #pragma unroll
    for (int mt = 0; mt < 2; mt++) {
        int rbase = row0 + wr * 32 + mt * 16;
        #pragma unroll
        for (int j = 0; j < 4; j++) {
            int cp = wc * 16 + j * 4 + t4;   // float2 column index (0..63)
            int r0 = rbase + g, r1 = rbase + g + 8;
            if (r0 < NN)
                ((float2*)g_h1)[(size_t)r0 * 64 + cp] = make_float2(d[mt][j][0], d[mt][j][1]);
            if (r1 < NN)
                ((float2*)g_h1)[(size_t)r1 * 64 + cp] = make_float2(d[mt][j][2], d[mt][j][3]);
        }
    }
}

// ---------------- layer-1 aggregate: warp-per-dst CSR gather -----------------
__global__ void __launch_bounds__(256) k_agg1(const float* __restrict__ b1) {
    int w = (blockIdx.x * 256 + threadIdx.x) >> 5;
    int lane = threadIdx.x & 31;
    if (w >= NN) return;
    int e = g_rowp[w], end = g_cur[w];
    float did = g_dinv[w];
    const float4* H = (const float4*)g_h1;

    float4 acc = ((const float4*)b1)[lane];
    float4 self = H[(size_t)w * 32 + lane];
    float d2 = did * did;
    acc.x = fmaf(self.x, d2, acc.x);
    acc.y = fmaf(self.y, d2, acc.y);
    acc.z = fmaf(self.z, d2, acc.z);
    acc.w = fmaf(self.w, d2, acc.w);

    int s = (e < end) ? g_nbr[e] : 0;
    while (e < end) {
        int sn = (e + 1 < end) ? g_nbr[e + 1] : 0;
        float nm = did * g_dinv[s];
        float4 v = H[(size_t)s * 32 + lane];
        acc.x = fmaf(v.x, nm, acc.x);
        acc.y = fmaf(v.y, nm, acc.y);
        acc.z = fmaf(v.z, nm, acc.z);
        acc.w = fmaf(v.w, nm, acc.w);
        s = sn;
        e++;
    }
    ((float4*)g_agg1)[(size_t)w * 32 + lane] = acc;
}

// ---------------- GEMM2: h2 = relu(agg1) @ W2  (100000x128 @ 128x40) --------
__global__ void __launch_bounds__(160) k_gemm2(const float* __restrict__ W2) {
    __shared__ u64 Ws2[64 * 20];
    __shared__ u64 Xs2[64 * 64];
    int t = threadIdx.x;
    int tx = t % 20, tg = t / 20;
    int row0 = blockIdx.x * 64;

    u64 acc[8];
    #pragma unroll
    for (int r = 0; r < 8; r++) acc[r] = 0ULL;

    for (int kt = 0; kt < 2; kt++) {
        const float2* Wg = (const float2*)(W2 + (size_t)(kt * 64) * 40);
        for (int i = t; i < 1280; i += 160) {
            float2 w = Wg[i];
            Ws2[i] = pack2(w.x, w.y);
        }
        for (int i = t; i < 4096; i += 160) {
            int r = i >> 6, k = i & 63;
            int row = row0 + r; if (row >= NN) row = NN - 1;
            float v = fmaxf(g_agg1[(size_t)row * FH + kt * 64 + k], 0.f);
            Xs2[i] = pack2(v, v);
        }
        __syncthreads();

        #pragma unroll
        for (int k = 0; k < 64; k += 2) {
            u64 w0 = Ws2[k * 20 + tx];
            u64 w1 = Ws2[(k + 1) * 20 + tx];
            #pragma unroll
            for (int r = 0; r < 8; r++) {
                ulonglong2 xv = *(const ulonglong2*)&Xs2[(tg * 8 + r) * 64 + k];
                acc[r] = ffma2(xv.x, w0, acc[r]);
                acc[r] = ffma2(xv.y, w1, acc[r]);
            }
        }
        __syncthreads();
    }

    #pragma unroll
    for (int r = 0; r < 8; r++) {
        int row = row0 + tg * 8 + r;
        if (row < NN)
            ((float2*)g_h2)[(size_t)row * 20 + tx] = unpack2(acc[r]);
    }
}

// ---------------- layer-2 aggregate: 10-threads-per-dst CSR gather -----------
__global__ void __launch_bounds__(320) k_agg2(const float* __restrict__ b2) {
    int idx = blockIdx.x * 320 + threadIdx.x;
    int w = idx / 10, c = idx % 10;
    if (w >= NN) return;
    int e = g_rowp[w], end = g_cur[w];
    float did = g_dinv[w];
    const float4* H = (const float4*)g_h2;

    float4 acc = ((const float4*)b2)[c];
    float4 self = H[(size_t)w * 10 + c];
    float d2 = did * did;
    acc.x = fmaf(self.x, d2, acc.x);
    acc.y = fmaf(self.y, d2, acc.y);
    acc.z = fmaf(self.z, d2, acc.z);
    acc.w = fmaf(self.w, d2, acc.w);

    int s = (e < end) ? g_nbr[e] : 0;
    while (e < end) {
        int sn = (e + 1 < end) ? g_nbr[e + 1] : 0;
        float nm = did * g_dinv[s];
        float4 v = H[(size_t)s * 10 + c];
        acc.x = fmaf(v.x, nm, acc.x);
        acc.y = fmaf(v.y, nm, acc.y);
        acc.z = fmaf(v.z, nm, acc.z);
        acc.w = fmaf(v.w, nm, acc.w);
        s = sn;
        e++;
    }
    ((float4*)g_agg2)[(size_t)w * 10 + c] = acc;
}

// ---------------- log_softmax, warp per row ----------------------------------
__global__ void k_lsm(float* __restrict__ out) {
    int row = (blockIdx.x * blockDim.x + threadIdx.x) >> 5;
    int lane = threadIdx.x & 31;
    if (row < NN) {
        const float* in = g_agg2 + (size_t)row * FO;
        float v0 = in[lane];
        float v1 = (lane < 8) ? in[32 + lane] : -CUDART_INF_F;
        float m = fmaxf(v0, v1);
        #pragma unroll
        for (int o = 16; o; o >>= 1) m = fmaxf(m, __shfl_xor_sync(0xffffffffu, m, o));
        float s = expf(v0 - m) + ((lane < 8) ? expf(v1 - m) : 0.f);
        #pragma unroll
        for (int o = 16; o; o >>= 1) s += __shfl_xor_sync(0xffffffffu, s, o);
        float ls = m + logf(s);
        out[(size_t)row * FO + lane] = v0 - ls;
        if (lane < 8) out[(size_t)row * FO + 32 + lane] = v1 - ls;
    }
}

// ---------------- launch ------------------------------------------------------
extern "C" void kernel_launch(void* const* d_in, const int* in_sizes, int n_in,
                              void* d_out, int out_size) {
    const float* x  = (const float*)d_in[0];
    const void*  ei = d_in[1];
    const float* W1 = (const float*)d_in[2];
    const float* b1 = (const float*)d_in[3];
    const float* W2 = (const float*)d_in[4];
    const float* b2 = (const float*)d_in[5];
    float* out = (float*)d_out;
    int E = in_sizes[1] / 2;
    if (E > EMAX) E = EMAX;

    static int smem_set = 0;
    if (!smem_set) {
        cudaFuncSetAttribute(k_gemm1, cudaFuncAttributeMaxDynamicSharedMemorySize,
                             2 * TOT1 * 4);
        smem_set = 1;
    }

    k_deg<<<(E + 255) / 256, 256>>>(ei, E);                     // 0
    k_rowp<<<(NN + 255) / 256, 256>>>(W1);                      // 1 (+ W split)
    k_fill<<<(E + 255) / 256, 256>>>(ei, E);                    // 2
    k_gemm1<<<(NN + 127) / 128, 512, 2 * TOT1 * 4>>>(x, W1);    // 3 <- ncu window
    k_agg1<<<(NN + 7) / 8, 256>>>(b1);                          // 4
    k_gemm2<<<(NN + 63) / 64, 160>>>(W2);                       // 5
    k_agg2<<<(NN * 10 + 319) / 320, 320>>>(b2);                 // 6
    k_lsm<<<(NN + 7) / 8, 256>>>(out);                          // 7
}